// round 4
// baseline (speedup 1.0000x reference)
#include <cuda_runtime.h>
#include <cuda_bf16.h>

#define N_LABELS 30000
#define HIDDEN   1024
#define BATCH    256
#define N_EDGES  (N_LABELS - 1)

#define REC_PENALTY   1e-4
#define PROBA_PENALTY 1e-4

// ---------------- device scratch (no allocations allowed) ----------------
__device__ double g_acc_bce;
__device__ double g_acc_rec;
__device__ double g_acc_prob;
__device__ int    g_idx_is64;
__device__ int    g_par[N_EDGES];
__device__ int    g_chi[N_EDGES];

// ---------------- helpers ----------------
__device__ __forceinline__ float block_reduce_sum(float v) {
    __shared__ float red[32];
    int lane = threadIdx.x & 31;
    int wid  = threadIdx.x >> 5;
    int nwarps = (blockDim.x + 31) >> 5;
    #pragma unroll
    for (int o = 16; o > 0; o >>= 1) v += __shfl_down_sync(0xffffffffu, v, o);
    if (lane == 0) red[wid] = v;
    __syncthreads();
    v = (threadIdx.x < nwarps) ? red[threadIdx.x] : 0.0f;
    if (wid == 0) {
        #pragma unroll
        for (int o = 16; o > 0; o >>= 1) v += __shfl_down_sync(0xffffffffu, v, o);
    }
    __syncthreads();   // red[] reusable after this
    return v;          // valid in thread 0
}

// ---------------- kernel 0: init accumulators + detect index dtype ----------------
__global__ void init_detect_kernel(const void* par_raw) {
    if (threadIdx.x == 0 && blockIdx.x == 0) {
        g_acc_bce  = 0.0;
        g_acc_rec  = 0.0;
        g_acc_prob = 0.0;
        // If data is int64, every 8-byte word is a value in [0, 30000).
        // If data is int32, the upper 4 bytes of most words hold a random
        // index in [0,30000) -> as u64 the value is huge. Sample 64 words
        // (512B, safely within 29999*4 bytes).
        const unsigned long long* p = (const unsigned long long*)par_raw;
        int is64 = 1;
        for (int i = 0; i < 64; i++) {
            if (p[i] >= (unsigned long long)N_LABELS) { is64 = 0; break; }
        }
        g_idx_is64 = is64;
    }
}

// ---------------- kernel 1: convert indices to int32 scratch ----------------
__global__ void convert_idx_kernel(const void* par_raw, const void* chi_raw) {
    int i = blockIdx.x * blockDim.x + threadIdx.x;
    if (i >= N_EDGES) return;
    if (g_idx_is64) {
        g_par[i] = (int)((const long long*)par_raw)[i];
        g_chi[i] = (int)((const long long*)chi_raw)[i];
    } else {
        g_par[i] = ((const int*)par_raw)[i];
        g_chi[i] = ((const int*)chi_raw)[i];
    }
}

// ---------------- kernel 2: fused BCE + prob_reg (one block per batch row) ----------------
__global__ __launch_bounds__(1024, 1)
void bce_prob_kernel(const float* __restrict__ logits,
                     const float* __restrict__ targets) {
    extern __shared__ float sig[];   // N_LABELS floats = 120000 B
    const int b = blockIdx.x;
    const float4* lrow = (const float4*)(logits  + (size_t)b * N_LABELS);
    const float4* trow = (const float4*)(targets + (size_t)b * N_LABELS);

    // Phase 1: BCE partial + sigmoid into smem (N_LABELS/4 = 7500 float4's)
    float bacc = 0.0f;
    for (int n4 = threadIdx.x; n4 < N_LABELS / 4; n4 += blockDim.x) {
        float4 l = lrow[n4];
        float4 t = trow[n4];
        // softplus(l) - l*t, numerically stable: max(l,0) + log1p(exp(-|l|)) - l*t
        bacc += fmaxf(l.x, 0.0f) + log1pf(__expf(-fabsf(l.x))) - l.x * t.x;
        bacc += fmaxf(l.y, 0.0f) + log1pf(__expf(-fabsf(l.y))) - l.y * t.y;
        bacc += fmaxf(l.z, 0.0f) + log1pf(__expf(-fabsf(l.z))) - l.z * t.z;
        bacc += fmaxf(l.w, 0.0f) + log1pf(__expf(-fabsf(l.w))) - l.w * t.w;
        int n = n4 * 4;
        sig[n + 0] = 1.0f / (1.0f + __expf(-l.x));
        sig[n + 1] = 1.0f / (1.0f + __expf(-l.y));
        sig[n + 2] = 1.0f / (1.0f + __expf(-l.z));
        sig[n + 3] = 1.0f / (1.0f + __expf(-l.w));
    }
    __syncthreads();

    // Phase 2: prob_reg gathers from smem sigmoid cache
    float pacc = 0.0f;
    for (int e = threadIdx.x; e < N_EDGES; e += blockDim.x) {
        float d = sig[g_chi[e]] - sig[g_par[e]];
        pacc += fmaxf(d, 0.0f);
    }

    float bsum = block_reduce_sum(bacc);
    float psum = block_reduce_sum(pacc);
    if (threadIdx.x == 0) {
        atomicAdd(&g_acc_bce,  (double)bsum);
        atomicAdd(&g_acc_prob, (double)psum);
    }
}

// ---------------- kernel 3: rec_reg edge gather ----------------
#define EPB 4            // edges per block
__global__ __launch_bounds__(256)
void rec_kernel(const float* __restrict__ params) {
    const int e0 = blockIdx.x * EPB;
    float acc = 0.0f;
    #pragma unroll
    for (int k = 0; k < EPB; k++) {
        int e = e0 + k;
        if (e >= N_EDGES) break;
        const float4* rp = (const float4*)(params + (size_t)g_par[e] * HIDDEN);
        const float4* rc = (const float4*)(params + (size_t)g_chi[e] * HIDDEN);
        // HIDDEN/4 = 256 float4 per row, one per thread
        float4 a = rp[threadIdx.x];
        float4 c = rc[threadIdx.x];
        float dx = a.x - c.x, dy = a.y - c.y, dz = a.z - c.z, dw = a.w - c.w;
        acc += dx * dx + dy * dy + dz * dz + dw * dw;
    }
    float s = block_reduce_sum(acc);
    if (threadIdx.x == 0) atomicAdd(&g_acc_rec, (double)s);
}

// ---------------- kernel 4: finalize ----------------
__global__ void finalize_kernel(float* __restrict__ out) {
    if (threadIdx.x == 0 && blockIdx.x == 0) {
        double bce = g_acc_bce / ((double)BATCH * (double)N_LABELS);
        double loss = bce
                    + REC_PENALTY   * (0.5 * g_acc_rec)
                    + PROBA_PENALTY * g_acc_prob;
        out[0] = (float)loss;
    }
}

// ---------------- launch ----------------
extern "C" void kernel_launch(void* const* d_in, const int* in_sizes, int n_in,
                              void* d_out, int out_size) {
    const float* logits  = (const float*)d_in[0];
    const float* targets = (const float*)d_in[1];
    const float* params  = (const float*)d_in[2];
    const void*  par_raw = d_in[3];
    const void*  chi_raw = d_in[4];
    float* out = (float*)d_out;

    static bool attr_set = false;
    if (!attr_set) {
        cudaFuncSetAttribute(bce_prob_kernel,
                             cudaFuncAttributeMaxDynamicSharedMemorySize,
                             N_LABELS * (int)sizeof(float));
        attr_set = true;
    }

    init_detect_kernel<<<1, 32>>>(par_raw);
    convert_idx_kernel<<<(N_EDGES + 255) / 256, 256>>>(par_raw, chi_raw);
    bce_prob_kernel<<<BATCH, 1024, N_LABELS * sizeof(float)>>>(logits, targets);
    rec_kernel<<<(N_EDGES + EPB - 1) / EPB, 256>>>(params);
    finalize_kernel<<<1, 32>>>(out);
}

// round 5
// speedup vs baseline: 1.2987x; 1.2987x over previous
#include <cuda_runtime.h>
#include <cuda_bf16.h>

#define N_LABELS 30000
#define HIDDEN   1024
#define BATCH    256
#define N_EDGES  (N_LABELS - 1)
#define E_PAD    30720              /* padded edge count: 30*1024, 16-divisible */
#define CHUNK    16                 /* rec edges per work-steal grab */
#define BCE_BLOCKS (BATCH / 2)      /* 128 blocks, 2 rows each */
#define GRID_MAIN  152              /* one block per SM (GB300: 152 SMs) */

#define REC_PENALTY   1e-4
#define PROBA_PENALTY 1e-4

// ---------------- device scratch ----------------
__device__ double g_acc_bce;
__device__ double g_acc_rec;
__device__ double g_acc_prob;
__device__ int    g_ctr;
__device__ int2   g_edges[E_PAD];   // {parent, child}; padding = {0,0} (contributes 0)

// ---------------- helpers ----------------
__device__ __forceinline__ float block_reduce_sum(float v) {
    __shared__ float red[32];
    int lane = threadIdx.x & 31;
    int wid  = threadIdx.x >> 5;
    int nwarps = (blockDim.x + 31) >> 5;
    #pragma unroll
    for (int o = 16; o > 0; o >>= 1) v += __shfl_down_sync(0xffffffffu, v, o);
    if (lane == 0) red[wid] = v;
    __syncthreads();
    v = (threadIdx.x < nwarps) ? red[threadIdx.x] : 0.0f;
    if (wid == 0) {
        #pragma unroll
        for (int o = 16; o > 0; o >>= 1) v += __shfl_down_sync(0xffffffffu, v, o);
    }
    __syncthreads();
    return v;   // valid in thread 0
}

// one element of BCE + sigmoid
__device__ __forceinline__ void bce_elem(float l, float t, float& bacc, float& sig) {
    float z = __expf(-fabsf(l));                       // e^{-|l|} in (0,1]
    bacc += fmaxf(l, 0.0f) + __logf(1.0f + z) - l * t; // softplus(l) - l*t
    float inv = __fdividef(1.0f, 1.0f + z);
    sig = (l >= 0.0f ? 1.0f : z) * inv;                // sigmoid(l)
}

__device__ __forceinline__ unsigned pack_bf2(float a, float b) {
    __nv_bfloat162 h = __floats2bfloat162_rn(a, b);
    return *reinterpret_cast<unsigned*>(&h);
}

// ---------------- kernel A: detect dtype, convert+pad edges, zero accumulators ----------------
__global__ void prep_kernel(const void* par_raw, const void* chi_raw) {
    __shared__ int s_is64;
    int i = blockIdx.x * 256 + threadIdx.x;
    if (i == 0) { g_acc_bce = 0.0; g_acc_rec = 0.0; g_acc_prob = 0.0; g_ctr = 0; }
    if (threadIdx.x == 0) {
        // int64 indices: every 8B word < 30000. int32: upper half almost surely nonzero.
        const unsigned long long* p = (const unsigned long long*)par_raw;
        int is64 = 1;
        for (int k = 0; k < 64; k++)
            if (p[k] >= (unsigned long long)N_LABELS) { is64 = 0; break; }
        s_is64 = is64;
    }
    __syncthreads();
    if (i >= E_PAD) return;
    int2 e;
    if (i < N_EDGES) {
        if (s_is64) {
            e.x = (int)((const long long*)par_raw)[i];
            e.y = (int)((const long long*)chi_raw)[i];
        } else {
            e.x = ((const int*)par_raw)[i];
            e.y = ((const int*)chi_raw)[i];
        }
    } else {
        e = make_int2(0, 0);
    }
    g_edges[i] = e;
}

// ---------------- fused main kernel ----------------
// Blocks [0,128): BCE + prob_reg for batch rows {2b, 2b+1} (sigmoids cached in
// smem as interleaved bf16x2), then join rec work-stealing.
// Blocks [128,152): rec work-stealing immediately.
__global__ __launch_bounds__(1024, 1)
void fused_kernel(const float* __restrict__ logits,
                  const float* __restrict__ targets,
                  const float* __restrict__ params) {
    extern __shared__ unsigned sig2[];   // N_LABELS bf16x2 words = 120000 B
    __shared__ int s_base;
    const int tid = threadIdx.x;
    const int bid = blockIdx.x;

    if (bid < BCE_BLOCKS) {
        const int r0 = 2 * bid, r1 = r0 + 1;
        const float4* l0 = (const float4*)(logits  + (size_t)r0 * N_LABELS);
        const float4* l1 = (const float4*)(logits  + (size_t)r1 * N_LABELS);
        const float4* t0 = (const float4*)(targets + (size_t)r0 * N_LABELS);
        const float4* t1 = (const float4*)(targets + (size_t)r1 * N_LABELS);

        // Phase 1: BCE partials + bf16x2 sigmoid cache
        float bacc = 0.0f;
        for (int n4 = tid; n4 < N_LABELS / 4; n4 += 1024) {
            float4 a = l0[n4], b = l1[n4];
            float4 ta = t0[n4], tb = t1[n4];
            float s0, s1;
            uint4 o;
            bce_elem(a.x, ta.x, bacc, s0); bce_elem(b.x, tb.x, bacc, s1); o.x = pack_bf2(s0, s1);
            bce_elem(a.y, ta.y, bacc, s0); bce_elem(b.y, tb.y, bacc, s1); o.y = pack_bf2(s0, s1);
            bce_elem(a.z, ta.z, bacc, s0); bce_elem(b.z, tb.z, bacc, s1); o.z = pack_bf2(s0, s1);
            bce_elem(a.w, ta.w, bacc, s0); bce_elem(b.w, tb.w, bacc, s1); o.w = pack_bf2(s0, s1);
            ((uint4*)sig2)[n4] = o;
        }
        __syncthreads();

        // Phase 2: prob_reg gathers from smem (both rows per 4B LDS)
        float pacc = 0.0f;
        #pragma unroll 5
        for (int e = tid; e < E_PAD; e += 1024) {   // exactly 30 iterations
            int2 pc = g_edges[e];
            unsigned up = sig2[pc.x];   // parent
            unsigned uc = sig2[pc.y];   // child
            float2 p = __bfloat1622float2(*reinterpret_cast<__nv_bfloat162*>(&up));
            float2 c = __bfloat1622float2(*reinterpret_cast<__nv_bfloat162*>(&uc));
            pacc += fmaxf(c.x - p.x, 0.0f) + fmaxf(c.y - p.y, 0.0f);
        }

        float bsum = block_reduce_sum(bacc);
        float psum = block_reduce_sum(pacc);
        if (tid == 0) {
            atomicAdd(&g_acc_bce,  (double)bsum);
            atomicAdd(&g_acc_prob, (double)psum);
        }
    }

    // ---- rec_reg: work-steal edge chunks ----
    const float4* P4 = (const float4*)params;
    const int g = tid >> 8;      // edge lane within pass (0..3)
    const int x = tid & 255;     // float4 index within the 1024-elem row
    float racc = 0.0f;

    for (;;) {
        if (tid == 0) s_base = atomicAdd(&g_ctr, CHUNK);
        __syncthreads();
        int base = s_base;
        __syncthreads();
        if (base >= E_PAD) break;
        #pragma unroll
        for (int pass = 0; pass < 4; pass += 2) {
            int e0 = base + pass * 4 + g;
            int e1 = e0 + 4;
            int2 q0 = g_edges[e0];
            int2 q1 = g_edges[e1];
            float4 a0 = P4[(size_t)q0.x * (HIDDEN / 4) + x];
            float4 c0 = P4[(size_t)q0.y * (HIDDEN / 4) + x];
            float4 a1 = P4[(size_t)q1.x * (HIDDEN / 4) + x];
            float4 c1 = P4[(size_t)q1.y * (HIDDEN / 4) + x];
            float d;
            d = a0.x - c0.x; racc += d * d;
            d = a0.y - c0.y; racc += d * d;
            d = a0.z - c0.z; racc += d * d;
            d = a0.w - c0.w; racc += d * d;
            d = a1.x - c1.x; racc += d * d;
            d = a1.y - c1.y; racc += d * d;
            d = a1.z - c1.z; racc += d * d;
            d = a1.w - c1.w; racc += d * d;
        }
    }

    float rsum = block_reduce_sum(racc);
    if (tid == 0) atomicAdd(&g_acc_rec, (double)rsum);
}

// ---------------- finalize ----------------
__global__ void finalize_kernel(float* __restrict__ out) {
    if (threadIdx.x == 0 && blockIdx.x == 0) {
        double bce = g_acc_bce / ((double)BATCH * (double)N_LABELS);
        double loss = bce
                    + REC_PENALTY   * (0.5 * g_acc_rec)
                    + PROBA_PENALTY * g_acc_prob;
        out[0] = (float)loss;
    }
}

// ---------------- launch ----------------
extern "C" void kernel_launch(void* const* d_in, const int* in_sizes, int n_in,
                              void* d_out, int out_size) {
    const float* logits  = (const float*)d_in[0];
    const float* targets = (const float*)d_in[1];
    const float* params  = (const float*)d_in[2];
    const void*  par_raw = d_in[3];
    const void*  chi_raw = d_in[4];
    float* out = (float*)d_out;

    static bool attr_set = false;
    if (!attr_set) {
        cudaFuncSetAttribute(fused_kernel,
                             cudaFuncAttributeMaxDynamicSharedMemorySize,
                             N_LABELS * (int)sizeof(unsigned));
        attr_set = true;
    }

    prep_kernel<<<E_PAD / 256, 256>>>(par_raw, chi_raw);
    fused_kernel<<<GRID_MAIN, 1024, N_LABELS * sizeof(unsigned)>>>(logits, targets, params);
    finalize_kernel<<<1, 32>>>(out);
}